// round 12
// baseline (speedup 1.0000x reference)
#include <cuda_runtime.h>
#include <cuda_fp16.h>
#include <cstdint>

#define NN 10000
#define NE 50000
#define WD 64
#define DEPTH 4
#define KP2 4224          // 4096 (P) + 64 (S/bias) + 64 (h/root)
#define NROWS 10112       // 79 * 128, padded
#define MAXDEG 32
#define KSPLIT 6
#define KQ 704            // KP2 / 6
#define KSTEP 64
#define KSTEPS 11         // KQ / 64

typedef unsigned long long u64;

// ================= mma.sync / ldmatrix helpers ==============================
__device__ __forceinline__ uint32_t s2u(const void* p) {
    uint32_t a;
    asm("{ .reg .u64 t; cvta.to.shared.u64 t, %1; cvt.u32.u64 %0, t; }" : "=r"(a) : "l"(p));
    return a;
}
__device__ __forceinline__ void ldsm4(uint32_t* r, uint32_t addr) {
    asm volatile("ldmatrix.sync.aligned.m8n8.x4.shared.b16 {%0,%1,%2,%3}, [%4];"
        : "=r"(r[0]), "=r"(r[1]), "=r"(r[2]), "=r"(r[3]) : "r"(addr));
}
__device__ __forceinline__ void mma16816(float* c, const uint32_t* a, const uint32_t* b) {
    asm volatile(
        "mma.sync.aligned.m16n8k16.row.col.f32.f16.f16.f32 "
        "{%0,%1,%2,%3}, {%4,%5,%6,%7}, {%8,%9}, {%0,%1,%2,%3};"
        : "+f"(c[0]), "+f"(c[1]), "+f"(c[2]), "+f"(c[3])
        : "r"(a[0]), "r"(a[1]), "r"(a[2]), "r"(a[3]), "r"(b[0]), "r"(b[1]));
}

// ================= scratch =================================================
__device__ __half g_A[(size_t)NROWS * KP2];    // 85.4 MB single-fp16 A
__device__ __half g_B[WD * KP2];               // B^T [o][k] single fp16, 528 KB
__device__ float g_aggp[KSPLIT * NN * WD];     // K-split partials
__device__ float g_t[NE * WD];                 // relu(ea@k1+b1), edge order
__device__ float g_h[2][NN * WD];
__device__ int   g_fill[NN];                   // becomes in-degree after k_en
__device__ int   g_es_src[NN * MAXDEG];        // padded CSR: src per slot
__device__ int   g_es_eid[NN * MAXDEG];        // padded CSR: edge id per slot

// ================= setup kernels ===========================================
// fused: edge MLP + padded-CSR scatter + node MLP
__global__ void k_en(const float* __restrict__ ea, const int* __restrict__ ei,
                     const float* __restrict__ k1W, const float* __restrict__ k1b,
                     const float* __restrict__ x, const float* __restrict__ W1,
                     const float* __restrict__ b1) {
    int i = blockIdx.x * 256 + threadIdx.x;
    if (i < NE * WD) {
        int e = i >> 6, o = i & 63;
        float a0 = ea[e * 3 + 0], a1 = ea[e * 3 + 1], a2 = ea[e * 3 + 2];
        float t = fmaf(a0, k1W[o], fmaf(a1, k1W[64 + o], fmaf(a2, k1W[128 + o], k1b[o])));
        g_t[i] = t > 0.f ? t : 0.f;
        if (o == 0) {
            int dst = ei[NE + e];
            int pos = atomicAdd(&g_fill[dst], 1);
            if (pos < MAXDEG) {
                g_es_src[dst * MAXDEG + pos] = ei[e];
                g_es_eid[dst * MAXDEG + pos] = e;
            }
        }
    } else if (i < NE * WD + NN * WD) {
        int j = i - NE * WD;
        int n = j >> 6, o = j & 63;
        float v = fmaf(x[n * 3 + 0], W1[o],
                  fmaf(x[n * 3 + 1], W1[64 + o],
                  fmaf(x[n * 3 + 2], W1[128 + o], b1[o])));
        g_h[0][j] = v;
    }
}

// fused: B^T permute (single fp16) AND zero-pad A rows NN..NROWS
__global__ void k_prep(const float* __restrict__ k2W, const float* __restrict__ k2b,
                       const float* __restrict__ root) {
    int j = blockIdx.x * 256 + threadIdx.x;
    if (j < WD * KP2) {
        int o = j / KP2, k = j % KP2;
        float v;
        if (k < 4096) {
            int i = k >> 6, kq = k & 63;
            v = k2W[kq * 4096 + i * 64 + o];
        } else if (k < 4160) {
            v = k2b[(k - 4096) * 64 + o];
        } else {
            v = root[(k - 4160) * 64 + o];
        }
        g_B[j] = __float2half_rn(v);
    } else {
        int p = j - WD * KP2;
        if (p < (NROWS - NN) * KP2) g_A[(size_t)NN * KP2 + p] = __float2half_rn(0.f);
    }
}

// ================= per-iteration kernels ===================================
// A row n = [ invd*(sum_e h_src ⊗ t_e) | invd*(sum_e h_src) | h_n ], fp16.
__global__ void k_build(int cur) {
    __shared__ float sh[16][128];
    int n = blockIdx.x;
    int tid = threadIdx.x;
    int deg = g_fill[n];
    if (deg > MAXDEG) deg = MAXDEG;
    int ti = tid >> 4, tk = tid & 15;
    float acc[16];
#pragma unroll
    for (int p = 0; p < 16; p++) acc[p] = 0.f;
    float4 sacc = make_float4(0.f, 0.f, 0.f, 0.f);
    const float* __restrict__ h = g_h[cur];
    int ebase = n * MAXDEG;
    for (int base = 0; base < deg; base += 16) {
        int nb = min(16, deg - base);
        __syncthreads();
        for (int idx = tid; idx < nb * 128; idx += 256) {
            int j = idx >> 7, f = idx & 127;
            int sl = ebase + base + j;
            if (f < 64) sh[j][f] = h[g_es_src[sl] * 64 + f];
            else        sh[j][f] = g_t[g_es_eid[sl] * 64 + f - 64];
        }
        __syncthreads();
        for (int j = 0; j < nb; j++) {
            float4 hq = *(const float4*)&sh[j][ti * 4];
            float4 tq = *(const float4*)&sh[j][64 + tk * 4];
            acc[0]  = fmaf(hq.x, tq.x, acc[0]);  acc[1]  = fmaf(hq.x, tq.y, acc[1]);
            acc[2]  = fmaf(hq.x, tq.z, acc[2]);  acc[3]  = fmaf(hq.x, tq.w, acc[3]);
            acc[4]  = fmaf(hq.y, tq.x, acc[4]);  acc[5]  = fmaf(hq.y, tq.y, acc[5]);
            acc[6]  = fmaf(hq.y, tq.z, acc[6]);  acc[7]  = fmaf(hq.y, tq.w, acc[7]);
            acc[8]  = fmaf(hq.z, tq.x, acc[8]);  acc[9]  = fmaf(hq.z, tq.y, acc[9]);
            acc[10] = fmaf(hq.z, tq.z, acc[10]); acc[11] = fmaf(hq.z, tq.w, acc[11]);
            acc[12] = fmaf(hq.w, tq.x, acc[12]); acc[13] = fmaf(hq.w, tq.y, acc[13]);
            acc[14] = fmaf(hq.w, tq.z, acc[14]); acc[15] = fmaf(hq.w, tq.w, acc[15]);
            if (tk == 0) {
                sacc.x += hq.x; sacc.y += hq.y; sacc.z += hq.z; sacc.w += hq.w;
            }
        }
    }
    float inv = 1.0f / (float)(deg > 0 ? deg : 1);
    size_t rowo = (size_t)n * KP2;
#pragma unroll
    for (int di = 0; di < 4; di++) {
        __half2 p0 = __floats2half2_rn(acc[di * 4 + 0] * inv, acc[di * 4 + 1] * inv);
        __half2 p1 = __floats2half2_rn(acc[di * 4 + 2] * inv, acc[di * 4 + 3] * inv);
        uint2 v;
        v.x = *(uint32_t*)&p0;
        v.y = *(uint32_t*)&p1;
        *(uint2*)(g_A + rowo + (ti * 4 + di) * 64 + tk * 4) = v;
    }
    if (tk == 0) {
        __half2 s0 = __floats2half2_rn(sacc.x * inv, sacc.y * inv);
        __half2 s1 = __floats2half2_rn(sacc.z * inv, sacc.w * inv);
        uint2 v;
        v.x = *(uint32_t*)&s0;
        v.y = *(uint32_t*)&s1;
        *(uint2*)(g_A + rowo + 4096 + ti * 4) = v;
        float4 hq = *(const float4*)&h[n * 64 + ti * 4];
        __half2 h0 = __floats2half2_rn(hq.x, hq.y);
        __half2 h1 = __floats2half2_rn(hq.z, hq.w);
        v.x = *(uint32_t*)&h0;
        v.y = *(uint32_t*)&h1;
        *(uint2*)(g_A + rowo + 4160 + ti * 4) = v;
    }
}

// mma.sync fp16 GEMM, m32 warp tiles:
// block tile M=128 x N=64; 4 warps, each m32n64 (2 A frags share B frags).
// grid 79 x 6 = 474 blocks, 128 thr, 11 k64-steps.
#define PITCH 72                  // fp16 elems per smem row (64 + 8 pad = 144 B)
__global__ void __launch_bounds__(128) k_gemm() {
    __shared__ __half sA[128 * PITCH];
    __shared__ __half sB[64 * PITCH];

    int tid = threadIdx.x;
    int warp = tid >> 5, lane = tid & 31;
    int n0 = blockIdx.x * 128;
    int ks = blockIdx.y;
    int wm = warp * 32;

    uint32_t uA = s2u(sA), uB = s2u(sB);

    float c[16][4];
#pragma unroll
    for (int f = 0; f < 16; f++)
#pragma unroll
        for (int qq = 0; qq < 4; qq++) c[f][qq] = 0.f;

    uint32_t aoff0 = (uint32_t)(wm + (lane & 15)) * (PITCH * 2) + ((lane >> 4) * 16);
    uint32_t aoff1 = aoff0 + 16 * (PITCH * 2);
    uint32_t boffB = (uint32_t)((lane & 7) + ((lane >> 4) & 1) * 8) * (PITCH * 2)
                   + (((lane >> 3) & 1) * 16);

    int kb = ks * KQ;
    for (int step = 0; step < KSTEPS; step++, kb += KSTEP) {
        __syncthreads();
        // A: 128 rows x 8 units(16B) = 1024; B: 64 x 8 = 512
#pragma unroll
        for (int idx = tid; idx < 1024; idx += 128) {
            int r = idx >> 3, u = idx & 7;
            size_t ga = (size_t)(n0 + r) * KP2 + kb + u * 8;
            *(uint4*)(sA + r * PITCH + u * 8) = *(const uint4*)(g_A + ga);
        }
#pragma unroll
        for (int idx = tid; idx < 512; idx += 128) {
            int r = idx >> 3, u = idx & 7;
            size_t gb = (size_t)r * KP2 + kb + u * 8;
            *(uint4*)(sB + r * PITCH + u * 8) = *(const uint4*)(g_B + gb);
        }
        __syncthreads();

#pragma unroll
        for (int kf = 0; kf < 4; kf++) {
            uint32_t koff = kf * 32;   // 16 fp16 = 32 B
            uint32_t a0[4], a1[4];
            ldsm4(a0, uA + aoff0 + koff);
            ldsm4(a1, uA + aoff1 + koff);
#pragma unroll
            for (int ng = 0; ng < 4; ng++) {
                uint32_t rowoff = (uint32_t)(ng * 16) * (PITCH * 2);
                uint32_t b[4];
                ldsm4(b, uB + boffB + rowoff + koff);
                mma16816(c[ng * 2 + 0], a0, b + 0);
                mma16816(c[ng * 2 + 1], a0, b + 2);
                mma16816(c[8 + ng * 2 + 0], a1, b + 0);
                mma16816(c[8 + ng * 2 + 1], a1, b + 2);
            }
        }
    }

    float* outp = g_aggp + (size_t)ks * NN * 64;
#pragma unroll
    for (int half16 = 0; half16 < 2; half16++) {
#pragma unroll
        for (int f = 0; f < 8; f++) {
            int ng = f >> 1, half = f & 1;
            int col = ng * 16 + half * 8 + (lane & 3) * 2;
            int r0 = n0 + wm + half16 * 16 + (lane >> 2);
            float* cc = c[half16 * 8 + f];
            if (r0 < NN) *(float2*)(outp + r0 * 64 + col) = make_float2(cc[0], cc[1]);
            int r1 = r0 + 8;
            if (r1 < NN) *(float2*)(outp + r1 * 64 + col) = make_float2(cc[2], cc[3]);
        }
    }
}

// h' = relu(sum of 6 partials + conv_b)
__global__ void k_comb(const float* __restrict__ cb, int nxt) {
    int i = blockIdx.x * 256 + threadIdx.x;
    if (i >= NN * 64) return;
    int o = i & 63;
    float v = cb[o];
#pragma unroll
    for (int s = 0; s < KSPLIT; s++) v += g_aggp[(size_t)s * NN * 64 + i];
    g_h[nxt][i] = v > 0.f ? v : 0.f;
}

__global__ void k_out(const float* __restrict__ w2, const float* __restrict__ b2,
                      float* __restrict__ out, int cur) {
    int warp = threadIdx.x >> 5, lane = threadIdx.x & 31;
    int n = blockIdx.x * 8 + warp;
    if (n >= NN) return;
    const float* h = g_h[cur] + n * 64;
    float s = h[lane] * w2[lane] + h[32 + lane] * w2[32 + lane];
#pragma unroll
    for (int d = 16; d; d >>= 1) s += __shfl_xor_sync(0xffffffff, s, d);
    if (lane == 0) out[n] = s + b2[0];
}

// ================= launch ==================================================
extern "C" void kernel_launch(void* const* d_in, const int* in_sizes, int n_in,
                              void* d_out, int out_size) {
    const float* x    = (const float*)d_in[0];
    const int*   ei   = (const int*)  d_in[1];
    const float* ea   = (const float*)d_in[2];
    const float* fc1W = (const float*)d_in[3];
    const float* fc1b = (const float*)d_in[4];
    const float* k1W  = (const float*)d_in[5];
    const float* k1b  = (const float*)d_in[6];
    const float* k2W  = (const float*)d_in[7];
    const float* k2b  = (const float*)d_in[8];
    const float* root = (const float*)d_in[9];
    const float* cb   = (const float*)d_in[10];
    const float* fc2W = (const float*)d_in[11];
    const float* fc2b = (const float*)d_in[12];
    float* out = (float*)d_out;

    void* p_fill = nullptr;
    cudaGetSymbolAddress(&p_fill, g_fill);
    cudaMemsetAsync(p_fill, 0, NN * sizeof(int));

    const int prep_threads = WD * KP2 + (NROWS - NN) * KP2;
    dim3 gg(NROWS / 128, KSPLIT);
    int cur = 0;

    // launch index:  0=k_en  1=k_build  2=k_prep  3=k_gemm (ncu capture slot)
    k_en<<<((NE + NN) * WD + 255) / 256, 256>>>(ea, ei, k1W, k1b, x, fc1W, fc1b);
    for (int d = 0; d < DEPTH; d++) {
        k_build<<<NN, 256>>>(cur);
        if (d == 0) k_prep<<<(prep_threads + 255) / 256, 256>>>(k2W, k2b, root);
        k_gemm<<<gg, 128>>>();
        k_comb<<<(NN * 64 + 255) / 256, 256>>>(cb, cur ^ 1);
        cur ^= 1;
    }
    k_out<<<(NN + 7) / 8, 256>>>(fc2W, fc2b, out, cur);
}

// round 13
// speedup vs baseline: 1.0779x; 1.0779x over previous
#include <cuda_runtime.h>
#include <cuda_fp16.h>
#include <cstdint>

#define NN 10000
#define NE 50000
#define WD 64
#define DEPTH 4
#define KP2 4224          // 4096 (P) + 64 (S/bias) + 64 (h/root)
#define NROWS 10112       // 158 * 64, padded
#define MAXDEG 32
#define KSPLIT 6
#define KQ 704            // KP2 / 6
#define KSTEP 64
#define KSTEPS 11         // KQ / 64

typedef unsigned long long u64;

// ================= mma.sync / ldmatrix helpers ==============================
__device__ __forceinline__ uint32_t s2u(const void* p) {
    uint32_t a;
    asm("{ .reg .u64 t; cvta.to.shared.u64 t, %1; cvt.u32.u64 %0, t; }" : "=r"(a) : "l"(p));
    return a;
}
__device__ __forceinline__ void ldsm4(uint32_t* r, uint32_t addr) {
    asm volatile("ldmatrix.sync.aligned.m8n8.x4.shared.b16 {%0,%1,%2,%3}, [%4];"
        : "=r"(r[0]), "=r"(r[1]), "=r"(r[2]), "=r"(r[3]) : "r"(addr));
}
__device__ __forceinline__ void mma16816(float* c, const uint32_t* a, const uint32_t* b) {
    asm volatile(
        "mma.sync.aligned.m16n8k16.row.col.f32.f16.f16.f32 "
        "{%0,%1,%2,%3}, {%4,%5,%6,%7}, {%8,%9}, {%0,%1,%2,%3};"
        : "+f"(c[0]), "+f"(c[1]), "+f"(c[2]), "+f"(c[3])
        : "r"(a[0]), "r"(a[1]), "r"(a[2]), "r"(a[3]), "r"(b[0]), "r"(b[1]));
}

// ================= scratch =================================================
__device__ __half g_A[(size_t)NROWS * KP2];    // 85.4 MB single-fp16 A
__device__ __half g_B[WD * KP2];               // B^T [o][k] single fp16, 528 KB
__device__ float g_aggp[KSPLIT * NN * WD];     // K-split partials
__device__ float g_t[NE * WD];                 // relu(ea@k1+b1), edge order
__device__ float g_h[2][NN * WD];
__device__ int   g_fill[NN];                   // becomes in-degree after k_en
__device__ int   g_es_src[NN * MAXDEG];        // padded CSR: src per slot
__device__ int   g_es_eid[NN * MAXDEG];        // padded CSR: edge id per slot

// ================= setup kernels ===========================================
// fused: edge MLP + padded-CSR scatter + node MLP
__global__ void k_en(const float* __restrict__ ea, const int* __restrict__ ei,
                     const float* __restrict__ k1W, const float* __restrict__ k1b,
                     const float* __restrict__ x, const float* __restrict__ W1,
                     const float* __restrict__ b1) {
    int i = blockIdx.x * 256 + threadIdx.x;
    if (i < NE * WD) {
        int e = i >> 6, o = i & 63;
        float a0 = ea[e * 3 + 0], a1 = ea[e * 3 + 1], a2 = ea[e * 3 + 2];
        float t = fmaf(a0, k1W[o], fmaf(a1, k1W[64 + o], fmaf(a2, k1W[128 + o], k1b[o])));
        g_t[i] = t > 0.f ? t : 0.f;
        if (o == 0) {
            int dst = ei[NE + e];
            int pos = atomicAdd(&g_fill[dst], 1);
            if (pos < MAXDEG) {
                g_es_src[dst * MAXDEG + pos] = ei[e];
                g_es_eid[dst * MAXDEG + pos] = e;
            }
        }
    } else if (i < NE * WD + NN * WD) {
        int j = i - NE * WD;
        int n = j >> 6, o = j & 63;
        float v = fmaf(x[n * 3 + 0], W1[o],
                  fmaf(x[n * 3 + 1], W1[64 + o],
                  fmaf(x[n * 3 + 2], W1[128 + o], b1[o])));
        g_h[0][j] = v;
    }
}

// fused: B^T permute (single fp16) AND zero-pad A rows NN..NROWS
__global__ void k_prep(const float* __restrict__ k2W, const float* __restrict__ k2b,
                       const float* __restrict__ root) {
    int j = blockIdx.x * 256 + threadIdx.x;
    if (j < WD * KP2) {
        int o = j / KP2, k = j % KP2;
        float v;
        if (k < 4096) {
            int i = k >> 6, kq = k & 63;
            v = k2W[kq * 4096 + i * 64 + o];
        } else if (k < 4160) {
            v = k2b[(k - 4096) * 64 + o];
        } else {
            v = root[(k - 4160) * 64 + o];
        }
        g_B[j] = __float2half_rn(v);
    } else {
        int p = j - WD * KP2;
        if (p < (NROWS - NN) * KP2) g_A[(size_t)NN * KP2 + p] = __float2half_rn(0.f);
    }
}

// ================= per-iteration kernels ===================================
// A row n = [ invd*(sum_e h_src ⊗ t_e) | invd*(sum_e h_src) | h_n ], fp16.
__global__ void k_build(int cur) {
    __shared__ float sh[16][128];
    int n = blockIdx.x;
    int tid = threadIdx.x;
    int deg = g_fill[n];
    if (deg > MAXDEG) deg = MAXDEG;
    int ti = tid >> 4, tk = tid & 15;
    float acc[16];
#pragma unroll
    for (int p = 0; p < 16; p++) acc[p] = 0.f;
    float4 sacc = make_float4(0.f, 0.f, 0.f, 0.f);
    const float* __restrict__ h = g_h[cur];
    int ebase = n * MAXDEG;
    for (int base = 0; base < deg; base += 16) {
        int nb = min(16, deg - base);
        __syncthreads();
        for (int idx = tid; idx < nb * 128; idx += 256) {
            int j = idx >> 7, f = idx & 127;
            int sl = ebase + base + j;
            if (f < 64) sh[j][f] = h[g_es_src[sl] * 64 + f];
            else        sh[j][f] = g_t[g_es_eid[sl] * 64 + f - 64];
        }
        __syncthreads();
        for (int j = 0; j < nb; j++) {
            float4 hq = *(const float4*)&sh[j][ti * 4];
            float4 tq = *(const float4*)&sh[j][64 + tk * 4];
            acc[0]  = fmaf(hq.x, tq.x, acc[0]);  acc[1]  = fmaf(hq.x, tq.y, acc[1]);
            acc[2]  = fmaf(hq.x, tq.z, acc[2]);  acc[3]  = fmaf(hq.x, tq.w, acc[3]);
            acc[4]  = fmaf(hq.y, tq.x, acc[4]);  acc[5]  = fmaf(hq.y, tq.y, acc[5]);
            acc[6]  = fmaf(hq.y, tq.z, acc[6]);  acc[7]  = fmaf(hq.y, tq.w, acc[7]);
            acc[8]  = fmaf(hq.z, tq.x, acc[8]);  acc[9]  = fmaf(hq.z, tq.y, acc[9]);
            acc[10] = fmaf(hq.z, tq.z, acc[10]); acc[11] = fmaf(hq.z, tq.w, acc[11]);
            acc[12] = fmaf(hq.w, tq.x, acc[12]); acc[13] = fmaf(hq.w, tq.y, acc[13]);
            acc[14] = fmaf(hq.w, tq.z, acc[14]); acc[15] = fmaf(hq.w, tq.w, acc[15]);
            if (tk == 0) {
                sacc.x += hq.x; sacc.y += hq.y; sacc.z += hq.z; sacc.w += hq.w;
            }
        }
    }
    float inv = 1.0f / (float)(deg > 0 ? deg : 1);
    size_t rowo = (size_t)n * KP2;
#pragma unroll
    for (int di = 0; di < 4; di++) {
        __half2 p0 = __floats2half2_rn(acc[di * 4 + 0] * inv, acc[di * 4 + 1] * inv);
        __half2 p1 = __floats2half2_rn(acc[di * 4 + 2] * inv, acc[di * 4 + 3] * inv);
        uint2 v;
        v.x = *(uint32_t*)&p0;
        v.y = *(uint32_t*)&p1;
        *(uint2*)(g_A + rowo + (ti * 4 + di) * 64 + tk * 4) = v;
    }
    if (tk == 0) {
        __half2 s0 = __floats2half2_rn(sacc.x * inv, sacc.y * inv);
        __half2 s1 = __floats2half2_rn(sacc.z * inv, sacc.w * inv);
        uint2 v;
        v.x = *(uint32_t*)&s0;
        v.y = *(uint32_t*)&s1;
        *(uint2*)(g_A + rowo + 4096 + ti * 4) = v;
        float4 hq = *(const float4*)&h[n * 64 + ti * 4];
        __half2 h0 = __floats2half2_rn(hq.x, hq.y);
        __half2 h1 = __floats2half2_rn(hq.z, hq.w);
        v.x = *(uint32_t*)&h0;
        v.y = *(uint32_t*)&h1;
        *(uint2*)(g_A + rowo + 4160 + ti * 4) = v;
    }
}

// mma.sync fp16 GEMM, occupancy-focused:
// block M=64 x N=64, 256 thr = 8 warps of m16n32 (4 M-warps x 2 N-warps).
// Register prefetch double-buffer: next step's LDGs overlap current compute.
// grid 158 x 6 = 948 blocks, 11 k64-steps.
#define PITCH 72                  // fp16 elems per smem row (64 + 8 pad = 144 B)
__global__ void __launch_bounds__(256) k_gemm() {
    __shared__ __half sA[64 * PITCH];
    __shared__ __half sB[64 * PITCH];

    int tid = threadIdx.x;
    int warp = tid >> 5, lane = tid & 31;
    int n0 = blockIdx.x * 64;
    int ks = blockIdx.y;
    int wm = (warp >> 1) * 16;          // M offset 0..48
    int wn = (warp & 1) * 32;           // N offset 0 or 32

    uint32_t uA = s2u(sA), uB = s2u(sB);

    float c[4][4];
#pragma unroll
    for (int f = 0; f < 4; f++)
#pragma unroll
        for (int qq = 0; qq < 4; qq++) c[f][qq] = 0.f;

    uint32_t aoff = (uint32_t)(wm + (lane & 15)) * (PITCH * 2) + ((lane >> 4) * 16);
    uint32_t boffB = (uint32_t)(wn + (lane & 7) + ((lane >> 4) & 1) * 8) * (PITCH * 2)
                   + (((lane >> 3) & 1) * 16);

    // loader indices: A 512 uint4, B 512 uint4; 256 threads -> 2 each
    int lr = tid >> 3, lu = tid & 7;                 // A/B row, unit for first
    int lr2 = (tid + 256) >> 3, lu2 = (tid + 256) & 7;
    uint32_t sAo1 = (uint32_t)lr * PITCH + lu * 8;
    uint32_t sAo2 = (uint32_t)lr2 * PITCH + lu2 * 8;

    uint4 pa0, pa1, pb0, pb1;
    int kb = ks * KQ;
    // prefetch step 0
    {
        pa0 = *(const uint4*)(g_A + (size_t)(n0 + lr) * KP2 + kb + lu * 8);
        pa1 = *(const uint4*)(g_A + (size_t)(n0 + lr2) * KP2 + kb + lu2 * 8);
        pb0 = *(const uint4*)(g_B + (size_t)lr * KP2 + kb + lu * 8);
        pb1 = *(const uint4*)(g_B + (size_t)lr2 * KP2 + kb + lu2 * 8);
    }

    for (int step = 0; step < KSTEPS; step++) {
        __syncthreads();   // previous compute done; smem free
        *(uint4*)(sA + sAo1) = pa0;
        *(uint4*)(sA + sAo2) = pa1;
        *(uint4*)(sB + sAo1) = pb0;
        *(uint4*)(sB + sAo2) = pb1;
        __syncthreads();

        if (step + 1 < KSTEPS) {       // issue next step's LDGs now
            int kn = kb + KSTEP;
            pa0 = *(const uint4*)(g_A + (size_t)(n0 + lr) * KP2 + kn + lu * 8);
            pa1 = *(const uint4*)(g_A + (size_t)(n0 + lr2) * KP2 + kn + lu2 * 8);
            pb0 = *(const uint4*)(g_B + (size_t)lr * KP2 + kn + lu * 8);
            pb1 = *(const uint4*)(g_B + (size_t)lr2 * KP2 + kn + lu2 * 8);
        }

#pragma unroll
        for (int kf = 0; kf < 4; kf++) {
            uint32_t koff = kf * 32;   // 16 fp16 = 32 B
            uint32_t a[4];
            ldsm4(a, uA + aoff + koff);
#pragma unroll
            for (int ng = 0; ng < 2; ng++) {
                uint32_t rowoff = (uint32_t)(ng * 16) * (PITCH * 2);
                uint32_t b[4];
                ldsm4(b, uB + boffB + rowoff + koff);
                mma16816(c[ng * 2 + 0], a, b + 0);
                mma16816(c[ng * 2 + 1], a, b + 2);
            }
        }
        kb += KSTEP;
    }

    float* outp = g_aggp + (size_t)ks * NN * 64;
#pragma unroll
    for (int f = 0; f < 4; f++) {
        int ng = f >> 1, half = f & 1;
        int col = wn + ng * 16 + half * 8 + (lane & 3) * 2;
        int r0 = n0 + wm + (lane >> 2);
        if (r0 < NN) *(float2*)(outp + r0 * 64 + col) = make_float2(c[f][0], c[f][1]);
        int r1 = r0 + 8;
        if (r1 < NN) *(float2*)(outp + r1 * 64 + col) = make_float2(c[f][2], c[f][3]);
    }
}

// h' = relu(sum of 6 partials + conv_b)
__global__ void k_comb(const float* __restrict__ cb, int nxt) {
    int i = blockIdx.x * 256 + threadIdx.x;
    if (i >= NN * 64) return;
    int o = i & 63;
    float v = cb[o];
#pragma unroll
    for (int s = 0; s < KSPLIT; s++) v += g_aggp[(size_t)s * NN * 64 + i];
    g_h[nxt][i] = v > 0.f ? v : 0.f;
}

__global__ void k_out(const float* __restrict__ w2, const float* __restrict__ b2,
                      float* __restrict__ out, int cur) {
    int warp = threadIdx.x >> 5, lane = threadIdx.x & 31;
    int n = blockIdx.x * 8 + warp;
    if (n >= NN) return;
    const float* h = g_h[cur] + n * 64;
    float s = h[lane] * w2[lane] + h[32 + lane] * w2[32 + lane];
#pragma unroll
    for (int d = 16; d; d >>= 1) s += __shfl_xor_sync(0xffffffff, s, d);
    if (lane == 0) out[n] = s + b2[0];
}

// ================= launch ==================================================
extern "C" void kernel_launch(void* const* d_in, const int* in_sizes, int n_in,
                              void* d_out, int out_size) {
    const float* x    = (const float*)d_in[0];
    const int*   ei   = (const int*)  d_in[1];
    const float* ea   = (const float*)d_in[2];
    const float* fc1W = (const float*)d_in[3];
    const float* fc1b = (const float*)d_in[4];
    const float* k1W  = (const float*)d_in[5];
    const float* k1b  = (const float*)d_in[6];
    const float* k2W  = (const float*)d_in[7];
    const float* k2b  = (const float*)d_in[8];
    const float* root = (const float*)d_in[9];
    const float* cb   = (const float*)d_in[10];
    const float* fc2W = (const float*)d_in[11];
    const float* fc2b = (const float*)d_in[12];
    float* out = (float*)d_out;

    void* p_fill = nullptr;
    cudaGetSymbolAddress(&p_fill, g_fill);
    cudaMemsetAsync(p_fill, 0, NN * sizeof(int));

    const int prep_threads = WD * KP2 + (NROWS - NN) * KP2;
    dim3 gg(NROWS / 64, KSPLIT);
    int cur = 0;

    // launch index:  0=k_en  1=k_build  2=k_prep  3=k_gemm (ncu capture slot)
    k_en<<<((NE + NN) * WD + 255) / 256, 256>>>(ea, ei, k1W, k1b, x, fc1W, fc1b);
    for (int d = 0; d < DEPTH; d++) {
        k_build<<<NN, 256>>>(cur);
        if (d == 0) k_prep<<<(prep_threads + 255) / 256, 256>>>(k2W, k2b, root);
        k_gemm<<<gg, 256>>>();
        k_comb<<<(NN * 64 + 255) / 256, 256>>>(cb, cur ^ 1);
        cur ^= 1;
    }
    k_out<<<(NN + 7) / 8, 256>>>(fc2W, fc2b, out, cur);
}